// round 16
// baseline (speedup 1.0000x reference)
#include <cuda_runtime.h>
#include <math.h>
#include <stdint.h>

#define TT 512
#define BB 256
#define HH 128
#define XD 257
#define ZD 16
#define GG 512
#define RB 4
#define NCLUST (BB/RB)
#define XROWS (BB*XD)
#define NTH 512

__device__ float d_xT[(size_t)TT*BB*XD];
__device__ float d_gates[(size_t)TT*GG*BB];
__device__ float d_gx[(size_t)TT*BB*HH];
__device__ float d_u0[(size_t)TT*BB*HH];
__device__ float d_zbuf[(size_t)BB*TT*ZD];
__device__ float d_hdec[(size_t)BB*TT*HH];
__device__ float d_WTgx[HH*GG];
__device__ float d_WTgz[HH*GG];
__device__ float d_WTh [HH*GG];
__device__ float d_W0RT[HH*HH];   // [k][j]
__device__ float d_WihTgz[ZD*GG];
__device__ float d_WihTh [ZD*GG];
__device__ float d_bgx[GG];
__device__ float d_bgz[GG];
__device__ float d_bh [GG];

typedef unsigned long long u64;

__device__ __forceinline__ float tanha(float x) {
    float y; asm("tanh.approx.f32 %0, %1;" : "=f"(y) : "f"(x)); return y;
}
__device__ __forceinline__ float sigf(float x) { return fmaf(0.5f, tanha(0.5f*x), 0.5f); }
__device__ __forceinline__ u64 pk2(float lo, float hi) {
    u64 r; asm("mov.b64 %0, {%1, %2};" : "=l"(r) : "f"(lo), "f"(hi)); return r;
}
__device__ __forceinline__ void upk2(u64 v, float& lo, float& hi) {
    asm("mov.b64 {%0, %1}, %2;" : "=f"(lo), "=f"(hi) : "l"(v));
}
__device__ __forceinline__ u64 f2fma(u64 a, u64 b, u64 c) {
    u64 d; asm("fma.rn.f32x2 %0, %1, %2, %3;" : "=l"(d) : "l"(a), "l"(b), "l"(c)); return d;
}
__device__ __forceinline__ u64 add2(u64 a, u64 b) {
    u64 d; asm("add.rn.f32x2 %0, %1, %2;" : "=l"(d) : "l"(a), "l"(b)); return d;
}
__device__ __forceinline__ uint32_t s2u(const void* p) {
    uint32_t a; asm("{ .reg .u64 t; cvta.to.shared.u64 t, %1; cvt.u32.u64 %0, t; }" : "=r"(a) : "l"(p)); return a;
}
__device__ __forceinline__ uint32_t mapa_u32(uint32_t a, uint32_t rk) {
    uint32_t o; asm("mapa.shared::cluster.u32 %0, %1, %2;" : "=r"(o) : "r"(a), "r"(rk)); return o;
}
__device__ __forceinline__ void stpeer32(uint32_t a, float v) {
    asm volatile("st.shared::cluster.f32 [%0], %1;" :: "r"(a), "f"(v) : "memory");
}
__device__ __forceinline__ void stpeer64(uint32_t a, u64 v) {
    asm volatile("st.shared::cluster.b64 [%0], %1;" :: "r"(a), "l"(v) : "memory");
}
__device__ __forceinline__ void mbar_init(uint32_t a, uint32_t cnt) {
    asm volatile("mbarrier.init.shared.b64 [%0], %1;" :: "r"(a), "r"(cnt) : "memory");
}
__device__ __forceinline__ void mbar_arrive_local(uint32_t a) {
    asm volatile("mbarrier.arrive.shared.b64 _, [%0];" :: "r"(a) : "memory");
}
__device__ __forceinline__ void mbar_arrive_peer(uint32_t a) {
    asm volatile("mbarrier.arrive.release.cluster.shared::cluster.b64 _, [%0];" :: "r"(a) : "memory");
}
__device__ __forceinline__ void mbar_wait(uint32_t a, uint32_t ph) {
    uint32_t done;
    asm volatile("{\n\t.reg .pred p;\n\t"
        "mbarrier.try_wait.parity.acquire.cta.shared::cta.b64 p, [%1], %2;\n\t"
        "selp.b32 %0, 1, 0, p;\n\t}" : "=r"(done) : "r"(a), "r"(ph) : "memory");
    while (!done) {
        asm volatile("{\n\t.reg .pred p;\n\t"
            "mbarrier.try_wait.parity.acquire.cta.shared::cta.b64 p, [%1], %2, 0x989680;\n\t"
            "selp.b32 %0, 1, 0, p;\n\t}" : "=r"(done) : "r"(a), "r"(ph) : "memory");
    }
}
#define CLUSTER_SYNC() do { \
    asm volatile("barrier.cluster.arrive.aligned;" ::: "memory"); \
    asm volatile("barrier.cluster.wait.aligned;"   ::: "memory"); } while (0)

__device__ __forceinline__ int h_wr_off(int k, int r) {
    return ((k << 5) + (r << 3)) ^ (k & 0x70);
}
__device__ __forceinline__ void gate_hloop(const char* hb, int sw,
        const u64* wif2, const u64* wgo2, u64* aif, u64* ago) {
#pragma unroll
    for (int kk = 0; kk < 16; kk++) {
        int off = (kk*32) ^ sw;
        ulonglong2 h01 = *(const ulonglong2*)(hb + off);
        ulonglong2 h23 = *(const ulonglong2*)(hb + (off ^ 16));
        aif[0]=f2fma(wif2[kk],h01.x,aif[0]); aif[1]=f2fma(wif2[kk],h01.y,aif[1]);
        aif[2]=f2fma(wif2[kk],h23.x,aif[2]); aif[3]=f2fma(wif2[kk],h23.y,aif[3]);
        ago[0]=f2fma(wgo2[kk],h01.x,ago[0]); ago[1]=f2fma(wgo2[kk],h01.y,ago[1]);
        ago[2]=f2fma(wgo2[kk],h23.x,ago[2]); ago[3]=f2fma(wgo2[kk],h23.y,ago[3]);
    }
}
// rounds d=1,2 only; finish after row-selection with 2 shfl (d=4)
__device__ __forceinline__ void gate_reduce12(u64* aif, u64* ago) {
#pragma unroll
    for (int d = 1; d <= 2; d <<= 1)
#pragma unroll
        for (int r = 0; r < 4; r++) {
            aif[r]=add2(aif[r],__shfl_xor_sync(0xffffffffu,aif[r],d));
            ago[r]=add2(ago[r],__shfl_xor_sync(0xffffffffu,ago[r],d));
        }
}
__device__ __forceinline__ void gate_finish(int khx, const u64* aif, const u64* ago,
        float& gi, float& gf, float& gg, float& go_) {
    u64 t1=(khx&1)?aif[1]:aif[0], t2=(khx&1)?aif[3]:aif[2];
    u64 vif=(khx&2)?t2:t1;
    u64 u1=(khx&1)?ago[1]:ago[0], u2=(khx&1)?ago[3]:ago[2];
    u64 vgo=(khx&2)?u2:u1;
    vif = add2(vif, __shfl_xor_sync(0xffffffffu, vif, 4));
    vgo = add2(vgo, __shfl_xor_sync(0xffffffffu, vgo, 4));
    upk2(vif,gi,gf); upk2(vgo,gg,go_);
}

__global__ void prep_weights(const float* __restrict__ Whh_gx,
                             const float* __restrict__ bih_gx, const float* __restrict__ bhh_gx,
                             const float* __restrict__ Wih_gz, const float* __restrict__ Whh_gz,
                             const float* __restrict__ bih_gz, const float* __restrict__ bhh_gz,
                             const float* __restrict__ W0,
                             const float* __restrict__ Wih_h, const float* __restrict__ Whh_h,
                             const float* __restrict__ bih_h, const float* __restrict__ bhh_h)
{
    int idx = blockIdx.x*blockDim.x + threadIdx.x;
    int stride = gridDim.x*blockDim.x;
    for (int i = idx; i < GG*HH; i += stride) {
        int j = i / HH, k = i % HH;
        d_WTgx[k*GG + j] = Whh_gx[i];
        d_WTgz[k*GG + j] = Whh_gz[i];
        d_WTh [k*GG + j] = Whh_h [i];
    }
    for (int i = idx; i < HH*HH; i += stride) {
        int j = i / HH, k = i % HH;
        d_W0RT[k*HH + j] = W0[j*(2*HH) + HH + k];
    }
    for (int i = idx; i < GG*ZD; i += stride) {
        int j = i / ZD, k = i % ZD;
        d_WihTgz[k*GG + j] = Wih_gz[i];
        d_WihTh [k*GG + j] = Wih_h [i];
    }
    for (int i = idx; i < GG; i += stride) {
        d_bgx[i] = bih_gx[i] + bhh_gx[i];
        d_bgz[i] = bih_gz[i] + bhh_gz[i];
        d_bh [i] = bih_h [i] + bhh_h [i];
    }
}

__global__ void __launch_bounds__(256) transpose_x(const float* __restrict__ x)
{
    __shared__ float tile[32][33];
    int r0 = blockIdx.x*32, c0 = blockIdx.y*32;
    int tx = threadIdx.x & 31, ty = threadIdx.x >> 5;
#pragma unroll
    for (int i = 0; i < 32; i += 8)
        tile[ty+i][tx] = x[(size_t)(r0+ty+i)*TT + c0 + tx];
    __syncthreads();
#pragma unroll
    for (int i = 0; i < 32; i += 8)
        d_xT[(size_t)(c0+ty+i)*XROWS + r0 + tx] = tile[tx][ty+i];
}

template<int MODE>
__global__ void __launch_bounds__(256)
gemm_tn(const float* __restrict__ A, int lda,
        const float* __restrict__ Bw, int ldb,
        const float* __restrict__ bias,
        float* __restrict__ C, int M, int N, int K)
{
    const int BM = 128, BN = 64, BK = 16;
    __shared__ float As[BK][BM];
    __shared__ u64 Bs2[BK][BN];
    int tid = threadIdx.x;
    int bm = blockIdx.x*BM, bn = blockIdx.y*BN;
    int tm = (tid & 15)*8, tn = (tid >> 4)*4;
    u64 acc[4][4];
#pragma unroll
    for (int p = 0; p < 4; p++)
#pragma unroll
        for (int j = 0; j < 4; j++) acc[p][j] = 0ull;
    int ar = tid >> 1, ac = (tid & 1)*8;
    int br = tid >> 2, bc = (tid & 3)*4;
    for (int kk = 0; kk < K; kk += BK) {
#pragma unroll
        for (int i = 0; i < 8; i++) {
            int k = kk + ac + i;
            As[ac+i][ar] = (k < K) ? A[(size_t)(bm+ar)*lda + k] : 0.f;
        }
#pragma unroll
        for (int i = 0; i < 4; i++) {
            int k = kk + bc + i;
            float bv = (k < K && (bn+br) < N) ? Bw[(size_t)(bn+br)*ldb + k] : 0.f;
            Bs2[bc+i][br] = pk2(bv, bv);
        }
        __syncthreads();
#pragma unroll
        for (int k = 0; k < BK; k++) {
            ulonglong2 aA = *(const ulonglong2*)(&As[k][tm]);
            ulonglong2 aB = *(const ulonglong2*)(&As[k][tm+4]);
            ulonglong2 b01 = *(const ulonglong2*)(&Bs2[k][tn]);
            ulonglong2 b23 = *(const ulonglong2*)(&Bs2[k][tn+2]);
            acc[0][0] = f2fma(aA.x, b01.x, acc[0][0]);
            acc[1][0] = f2fma(aA.y, b01.x, acc[1][0]);
            acc[2][0] = f2fma(aB.x, b01.x, acc[2][0]);
            acc[3][0] = f2fma(aB.y, b01.x, acc[3][0]);
            acc[0][1] = f2fma(aA.x, b01.y, acc[0][1]);
            acc[1][1] = f2fma(aA.y, b01.y, acc[1][1]);
            acc[2][1] = f2fma(aB.x, b01.y, acc[2][1]);
            acc[3][1] = f2fma(aB.y, b01.y, acc[3][1]);
            acc[0][2] = f2fma(aA.x, b23.x, acc[0][2]);
            acc[1][2] = f2fma(aA.y, b23.x, acc[1][2]);
            acc[2][2] = f2fma(aB.x, b23.x, acc[2][2]);
            acc[3][2] = f2fma(aB.y, b23.x, acc[3][2]);
            acc[0][3] = f2fma(aA.x, b23.y, acc[0][3]);
            acc[1][3] = f2fma(aA.y, b23.y, acc[1][3]);
            acc[2][3] = f2fma(aB.x, b23.y, acc[2][3]);
            acc[3][3] = f2fma(aB.y, b23.y, acc[3][3]);
        }
        __syncthreads();
    }
#pragma unroll
    for (int j = 0; j < 4; j++) {
        int n = bn + tn + j;
        if (n >= N) continue;
        float bi = bias[n];
#pragma unroll
        for (int p = 0; p < 4; p++) {
            float v0, v1; upk2(acc[p][j], v0, v1);
            int m0 = bm + tm + 2*p;
            if (MODE == 0) {
                C[(size_t)m0*N + n]     = v0 + bi;
                C[(size_t)(m0+1)*N + n] = v1 + bi;
            } else if (MODE == 2) {
                int t = m0 >> 8, b = m0 & 255;
                C[((size_t)t*GG + n)*BB + b]     = v0 + bi;
                C[((size_t)t*GG + n)*BB + b + 1] = v1 + bi;
            } else {
                int b = m0 >> 9, t = m0 & 511;
                C[(size_t)b*XD*TT + (size_t)n*TT + t] = __expf(v0 + bi);
                int m1 = m0 + 1;
                b = m1 >> 9; t = m1 & 511;
                C[(size_t)b*XD*TT + (size_t)n*TT + t] = __expf(v1 + bi);
            }
        }
    }
}

// ===== LSTM smem (bytes): mbar 16 | h4d 3x4096 | z4d 3x512
#define SB_MB    0
#define SB_H4D   16
#define SB_Z4D   (16 + 12288)
#define SMB_LSTM (16 + 12288 + 1536)

__global__ void __launch_bounds__(NTH,1) __cluster_dims__(2,1,1)
lstm_gx_kernel()
{
    extern __shared__ char smc[];
    char* h4d = smc + SB_H4D;
    uint32_t mb = s2u(smc + SB_MB);
    int tid = threadIdx.x;
    int l = tid & 31, w = tid >> 5;
    int khx = l & 7;
    int hi  = w*4 + (l >> 3);
    uint32_t rank = blockIdx.x & 1u;
    int b0 = (blockIdx.x >> 1) * RB;
    int hig = (int)rank*64 + hi;

    u64 wif2[16], wgo2[16];
#pragma unroll
    for (int kk = 0; kk < 16; kk++) {
        int k = khx*16 + kk;
        wif2[kk] = pk2(d_WTgx[k*GG + hig],       d_WTgx[k*GG + 128 + hig]);
        wgo2[kk] = pk2(d_WTgx[k*GG + 256 + hig], d_WTgx[k*GG + 384 + hig]);
    }
    for (int i = tid; i < 1024; i += NTH) ((float*)h4d)[i] = 0.f;
    if (tid == 0) mbar_init(mb, 512);   // 256 local writers + 256 peer writers
    float c_ = 0.f;
    __syncthreads();
    CLUSTER_SYNC();
    uint32_t peer_base = mapa_u32(s2u(smc), rank ^ 1u);
    uint32_t mb_peer = peer_base + SB_MB;

    bool ldr = (khx == 0);
    float4 pgi, pgf, pgg, pgo;
    if (ldr) {
        const float* gp = d_gates + (size_t)(TT-1)*GG*BB + b0;
        pgi = *(const float4*)(gp + (size_t)hig*BB);
        pgf = *(const float4*)(gp + (size_t)(128+hig)*BB);
        pgg = *(const float4*)(gp + (size_t)(256+hig)*BB);
        pgo = *(const float4*)(gp + (size_t)(384+hig)*BB);
    }
    const int sw = khx << 4;
    int br = 0, bw = 1;

    for (int t = TT-1, s = 0; t >= 0; --t, ++s) {
        u64 aif[4], ago[4];
        if (ldr) {
            aif[0]=pk2(pgi.x,pgf.x); aif[1]=pk2(pgi.y,pgf.y);
            aif[2]=pk2(pgi.z,pgf.z); aif[3]=pk2(pgi.w,pgf.w);
            ago[0]=pk2(pgg.x,pgo.x); ago[1]=pk2(pgg.y,pgo.y);
            ago[2]=pk2(pgg.z,pgo.z); ago[3]=pk2(pgg.w,pgo.w);
            if (t > 0) {
                const float* gp = d_gates + (size_t)(t-1)*GG*BB + b0;
                pgi = *(const float4*)(gp + (size_t)hig*BB);
                pgf = *(const float4*)(gp + (size_t)(128+hig)*BB);
                pgg = *(const float4*)(gp + (size_t)(256+hig)*BB);
                pgo = *(const float4*)(gp + (size_t)(384+hig)*BB);
            }
        } else {
#pragma unroll
            for (int r = 0; r < 4; r++) { aif[r] = 0ull; ago[r] = 0ull; }
        }
        gate_hloop(h4d + br*4096 + khx*512, sw, wif2, wgo2, aif, ago);
        gate_reduce12(aif, ago);
        float gi, gf, gg, go_;
        gate_finish(khx, aif, ago, gi, gf, gg, go_);
        float hkeep = 0.f;
        if (khx < 4) {
            int r = khx;
            float i_ = sigf(gi), f_ = sigf(gf), g_ = tanha(gg), o_ = sigf(go_);
            c_ = f_*c_ + i_*g_;
            float h = o_*tanha(c_);
            hkeep = h;
            u64 hdup = pk2(h, h);
            int woff = bw*4096 + h_wr_off(hig, r);
            *(u64*)(h4d + woff) = hdup;
            stpeer64(peer_base + SB_H4D + (uint32_t)woff, hdup);
            mbar_arrive_peer(mb_peer);
            mbar_arrive_local(mb);
            d_gx[((size_t)t*BB + b0 + r)*HH + hig] = hkeep;
        }
        mbar_wait(mb, s & 1);
        br = bw; bw = (bw == 2) ? 0 : bw + 1;
    }
}

__global__ void __launch_bounds__(NTH,1) __cluster_dims__(2,1,1)
lstm_dec_kernel()
{
    extern __shared__ char smc[];
    char* h4d = smc + SB_H4D;
    char* z4d = smc + SB_Z4D;
    uint32_t mb = s2u(smc + SB_MB);
    int tid = threadIdx.x;
    int l = tid & 31, w = tid >> 5;
    int khx = l & 7;
    int hi  = w*4 + (l >> 3);
    uint32_t rank = blockIdx.x & 1u;
    int b0 = (blockIdx.x >> 1) * RB;
    int hig = (int)rank*64 + hi;

    u64 wif2[16], wgo2[16];
#pragma unroll
    for (int kk = 0; kk < 16; kk++) {
        int k = khx*16 + kk;
        wif2[kk] = pk2(d_WTh[k*GG + hig],       d_WTh[k*GG + 128 + hig]);
        wgo2[kk] = pk2(d_WTh[k*GG + 256 + hig], d_WTh[k*GG + 384 + hig]);
    }
    u64 wzif2[2], wzgo2[2];
#pragma unroll
    for (int jz = 0; jz < 2; jz++) {
        int zk = khx*2 + jz;
        wzif2[jz] = pk2(d_WihTh[zk*GG + hig],       d_WihTh[zk*GG + 128 + hig]);
        wzgo2[jz] = pk2(d_WihTh[zk*GG + 256 + hig], d_WihTh[zk*GG + 384 + hig]);
    }
    u64 bif2 = pk2(d_bh[hig],       d_bh[128 + hig]);
    u64 bgo2 = pk2(d_bh[256 + hig], d_bh[384 + hig]);

    for (int i = tid; i < 1024; i += NTH) ((float*)h4d)[i] = 0.f;
    float znext = 0.f;
    int zr = tid >> 4, zzi = tid & 15;
    if (tid < 64) {
        float z0 = d_zbuf[((size_t)(b0+zr)*TT + 0)*ZD + zzi];
        *(u64*)(z4d + zzi*32 + zr*8) = pk2(z0, z0);
        znext = d_zbuf[((size_t)(b0+zr)*TT + 1)*ZD + zzi];
    }
    if (tid == 0) mbar_init(mb, 512);
    float c_ = 0.f;
    __syncthreads();
    CLUSTER_SYNC();
    uint32_t peer_base = mapa_u32(s2u(smc), rank ^ 1u);
    uint32_t mb_peer = peer_base + SB_MB;
    const int sw = khx << 4;
    int br = 0, bw = 1;

    for (int t = 0, s = 0; t < TT; ++t, ++s) {
        if (tid < 64 && t+1 < TT) {
            *(u64*)(z4d + bw*512 + zzi*32 + zr*8) = pk2(znext, znext);
            if (t+2 < TT)
                znext = d_zbuf[((size_t)(b0+zr)*TT + (t+2))*ZD + zzi];
        }
        u64 aif[4], ago[4];
        if (khx == 0) {
#pragma unroll
            for (int r = 0; r < 4; r++) { aif[r] = bif2; ago[r] = bgo2; }
        } else {
#pragma unroll
            for (int r = 0; r < 4; r++) { aif[r] = 0ull; ago[r] = 0ull; }
        }
        const char* zb = z4d + br*512;
#pragma unroll
        for (int jz = 0; jz < 2; jz++) {
            int zk = khx*2 + jz;
            ulonglong2 z01 = *(const ulonglong2*)(zb + zk*32);
            ulonglong2 z23 = *(const ulonglong2*)(zb + zk*32 + 16);
            aif[0]=f2fma(wzif2[jz],z01.x,aif[0]); aif[1]=f2fma(wzif2[jz],z01.y,aif[1]);
            aif[2]=f2fma(wzif2[jz],z23.x,aif[2]); aif[3]=f2fma(wzif2[jz],z23.y,aif[3]);
            ago[0]=f2fma(wzgo2[jz],z01.x,ago[0]); ago[1]=f2fma(wzgo2[jz],z01.y,ago[1]);
            ago[2]=f2fma(wzgo2[jz],z23.x,ago[2]); ago[3]=f2fma(wzgo2[jz],z23.y,ago[3]);
        }
        gate_hloop(h4d + br*4096 + khx*512, sw, wif2, wgo2, aif, ago);
        gate_reduce12(aif, ago);
        float gi, gf, gg, go_;
        gate_finish(khx, aif, ago, gi, gf, gg, go_);
        if (khx < 4) {
            int r = khx;
            float i_ = sigf(gi), f_ = sigf(gf), g_ = tanha(gg), o_ = sigf(go_);
            c_ = f_*c_ + i_*g_;
            float h = o_*tanha(c_);
            u64 hdup = pk2(h, h);
            int woff = bw*4096 + h_wr_off(hig, r);
            *(u64*)(h4d + woff) = hdup;
            stpeer64(peer_base + SB_H4D + (uint32_t)woff, hdup);
            mbar_arrive_peer(mb_peer);
            mbar_arrive_local(mb);
            d_hdec[((size_t)(b0+r)*TT + t)*HH + hig] = h;
        }
        mbar_wait(mb, s & 1);
        br = bw; bw = (bw == 2) ? 0 : bw + 1;
    }
}

// ===== inference smem (bytes)
#define SBI_MBH  0
#define SBI_MBZ  8
#define SBI_H4D  16
#define SBI_Z4D  (16 + 12288)
#define SBI_H4P  (SBI_Z4D + 1536)
#define SBI_W0R  (SBI_H4P + 6144)
#define SBI_WHD  (SBI_W0R + 65536)
#define SBI_HM   (SBI_WHD + 16896)
#define SBI_MV   (SBI_HM + 1024)
#define SMB_INF  (SBI_MV + 256)

__global__ void __launch_bounds__(NTH,1) __cluster_dims__(2,1,1)
inference_kernel(const float* __restrict__ eps,
                 const float* __restrict__ Wm, const float* __restrict__ bm,
                 const float* __restrict__ Wv, const float* __restrict__ bv,
                 float* __restrict__ out_mean, float* __restrict__ out_logvar,
                 float* __restrict__ out_z)
{
    extern __shared__ char smc[];
    char*  h4d = smc + SBI_H4D;
    char*  z4d = smc + SBI_Z4D;
    float* h4p = (float*)(smc + SBI_H4P);
    float* W0R = (float*)(smc + SBI_W0R);
    float* whd = (float*)(smc + SBI_WHD);
    float* hm  = (float*)(smc + SBI_HM);
    float* mv  = (float*)(smc + SBI_MV);
    uint32_t mbh = s2u(smc + SBI_MBH);
    uint32_t mbz = s2u(smc + SBI_MBZ);
    int tid = threadIdx.x;
    int l = tid & 31, w = tid >> 5;
    int khx = l & 7;
    int hi  = w*4 + (l >> 3);
    uint32_t rank = blockIdx.x & 1u;
    int b0 = (blockIdx.x >> 1) * RB;
    int hig = (int)rank*64 + hi;

    u64 wif2[16], wgo2[16];
#pragma unroll
    for (int kk = 0; kk < 16; kk++) {
        int k = khx*16 + kk;
        wif2[kk] = pk2(d_WTgz[k*GG + hig],       d_WTgz[k*GG + 128 + hig]);
        wgo2[kk] = pk2(d_WTgz[k*GG + 256 + hig], d_WTgz[k*GG + 384 + hig]);
    }
    u64 wzif2[2], wzgo2[2];
#pragma unroll
    for (int jz = 0; jz < 2; jz++) {
        int zk = khx*2 + jz;
        wzif2[jz] = pk2(d_WihTgz[zk*GG + hig],       d_WihTgz[zk*GG + 128 + hig]);
        wzgo2[jz] = pk2(d_WihTgz[zk*GG + 256 + hig], d_WihTgz[zk*GG + 384 + hig]);
    }
    u64 bif2 = pk2(d_bgz[hig],       d_bgz[128 + hig]);
    u64 bgo2 = pk2(d_bgz[256 + hig], d_bgz[384 + hig]);

    for (int i = tid; i < HH*HH; i += NTH) W0R[i] = d_W0RT[i];
    for (int i = tid; i < 32*HH; i += NTH) {
        int row = i >> 7, k = i & 127;
        whd[row*132 + k] = (row < 16) ? Wm[row*HH + k] : Wv[(row-16)*HH + k];
    }
    int outv = tid >> 3, kq = tid & 7;
    int rr_h = (outv >> 5) & 1, head = (outv >> 4) & 1, zi_h = outv & 15;
    float hbias = head ? bv[zi_h] : bm[zi_h];
    int jm = tid & 127, rrm = (tid >> 7) & 1;
    int browm = b0 + rank*2 + rrm;
    int hidxm = rank*2 + rrm;
    int rr_z = (tid >> 4) & 1, zi_z = tid & 15;
    int brow_z = b0 + rank*2 + rr_z;

    for (int i = tid; i < 1024; i += NTH) ((float*)h4d)[i] = 0.f;
    for (int i = tid; i < 512; i += NTH)  h4p[i] = 0.f;
    if (tid == 0) { mbar_init(mbh, 512); mbar_init(mbz, 64); }
    float c_ = 0.f;
    __syncthreads();
    CLUSTER_SYNC();
    uint32_t peer_base = mapa_u32(s2u(smc), rank ^ 1u);
    uint32_t mbh_peer = peer_base + SBI_MBH;
    uint32_t mbz_peer = peer_base + SBI_MBZ;

    float u0pf = 0.f, epf = 0.f;
    if (tid < 256) u0pf = d_u0[((size_t)0*BB + browm)*HH + jm];
    if (tid < 32)  epf  = eps[((size_t)0*BB + brow_z)*ZD + zi_z];

    const int sw = khx << 4;
    int br = 0, bw = 1;

    for (int t = 0, s = 0; t < TT; ++t, ++s) {
        float u0c = u0pf, ec = epf;
        if (t+1 < TT) {
            if (tid < 256) u0pf = d_u0[((size_t)(t+1)*BB + browm)*HH + jm];
            if (tid < 32)  epf  = eps[((size_t)(t+1)*BB + brow_z)*ZD + zi_z];
        }
        if (tid < 256) {
            const float* hp = h4p + br*512 + hidxm;
            float a0 = u0c, a1 = 0.f, a2 = 0.f, a3 = 0.f;
#pragma unroll
            for (int k = 0; k < HH; k += 4) {
                a0 += W0R[k*HH + jm]     * hp[k*4];
                a1 += W0R[(k+1)*HH + jm] * hp[(k+1)*4];
                a2 += W0R[(k+2)*HH + jm] * hp[(k+2)*4];
                a3 += W0R[(k+3)*HH + jm] * hp[(k+3)*4];
            }
            hm[rrm*HH + jm] = tanha((a0+a1) + (a2+a3));
        }
        __syncthreads();
        {
            const float* wrow = whd + (head*16 + zi_h)*132 + kq*16;
            const float* hr   = hm + rr_h*HH + kq*16;
            float s0=0.f, s1=0.f, s2=0.f, s3=0.f;
#pragma unroll
            for (int kk = 0; kk < 16; kk += 4) {
                float4 wv4 = *(const float4*)(wrow + kk);
                float4 hv4 = *(const float4*)(hr + kk);
                s0 += wv4.x*hv4.x; s1 += wv4.y*hv4.y;
                s2 += wv4.z*hv4.z; s3 += wv4.w*hv4.w;
            }
            float acc = (s0+s1) + (s2+s3);
            acc += __shfl_xor_sync(0xffffffffu, acc, 1);
            acc += __shfl_xor_sync(0xffffffffu, acc, 2);
            acc += __shfl_xor_sync(0xffffffffu, acc, 4);
            if (kq == 0) mv[outv] = acc + hbias;
        }
        __syncthreads();
        int zslot = br*512;
        if (tid < 32) {
            float mn = mv[rr_z*32 + zi_z];
            float lv = mv[rr_z*32 + 16 + zi_z];
            float zv = ec*__expf(0.5f*lv) + mn;
            u64 zdup = pk2(zv, zv);
            int zo = zslot + zi_z*32 + (int)(rank*2 + rr_z)*8;
            *(u64*)(z4d + zo) = zdup;
            stpeer64(peer_base + SBI_Z4D + (uint32_t)zo, zdup);
            mbar_arrive_peer(mbz_peer);
            mbar_arrive_local(mbz);
            size_t oidx = (size_t)brow_z*ZD*TT + (size_t)zi_z*TT + t;
            out_mean[oidx]   = mn;
            out_logvar[oidx] = lv;
            out_z[oidx]      = zv;
            d_zbuf[((size_t)brow_z*TT + t)*ZD + zi_z] = zv;
        }
        mbar_wait(mbz, s & 1);
        u64 aif[4], ago[4];
        if (khx == 0) {
#pragma unroll
            for (int r = 0; r < 4; r++) { aif[r] = bif2; ago[r] = bgo2; }
        } else {
#pragma unroll
            for (int r = 0; r < 4; r++) { aif[r] = 0ull; ago[r] = 0ull; }
        }
        const char* zb = z4d + zslot;
#pragma unroll
        for (int jz = 0; jz < 2; jz++) {
            int zk = khx*2 + jz;
            ulonglong2 z01 = *(const ulonglong2*)(zb + zk*32);
            ulonglong2 z23 = *(const ulonglong2*)(zb + zk*32 + 16);
            aif[0]=f2fma(wzif2[jz],z01.x,aif[0]); aif[1]=f2fma(wzif2[jz],z01.y,aif[1]);
            aif[2]=f2fma(wzif2[jz],z23.x,aif[2]); aif[3]=f2fma(wzif2[jz],z23.y,aif[3]);
            ago[0]=f2fma(wzgo2[jz],z01.x,ago[0]); ago[1]=f2fma(wzgo2[jz],z01.y,ago[1]);
            ago[2]=f2fma(wzgo2[jz],z23.x,ago[2]); ago[3]=f2fma(wzgo2[jz],z23.y,ago[3]);
        }
        gate_hloop(h4d + br*4096 + khx*512, sw, wif2, wgo2, aif, ago);
        gate_reduce12(aif, ago);
        float gi, gf, gg, go_;
        gate_finish(khx, aif, ago, gi, gf, gg, go_);
        if (khx < 4) {
            int r = khx;
            float i_ = sigf(gi), f_ = sigf(gf), g_ = tanha(gg), o_ = sigf(go_);
            c_ = f_*c_ + i_*g_;
            float h = o_*tanha(c_);
            u64 hdup = pk2(h, h);
            int woff = bw*4096 + h_wr_off(hig, r);
            *(u64*)(h4d + woff) = hdup;
            stpeer64(peer_base + SBI_H4D + (uint32_t)woff, hdup);
            int poff = bw*512 + hig*4 + r;
            h4p[poff] = h;
            stpeer32(peer_base + SBI_H4P + (uint32_t)poff*4u, h);
            mbar_arrive_peer(mbh_peer);
            mbar_arrive_local(mbh);
        }
        mbar_wait(mbh, s & 1);
        br = bw; bw = (bw == 2) ? 0 : bw + 1;
    }
}

extern "C" void kernel_launch(void* const* d_in, const int* in_sizes, int n_in,
                              void* d_out, int out_size)
{
    (void)in_sizes; (void)n_in; (void)out_size;
    const float* x      = (const float*)d_in[0];
    const float* eps    = (const float*)d_in[1];
    const float* Wih_gx = (const float*)d_in[2];
    const float* Whh_gx = (const float*)d_in[3];
    const float* bih_gx = (const float*)d_in[4];
    const float* bhh_gx = (const float*)d_in[5];
    const float* Wih_gz = (const float*)d_in[6];
    const float* Whh_gz = (const float*)d_in[7];
    const float* bih_gz = (const float*)d_in[8];
    const float* bhh_gz = (const float*)d_in[9];
    const float* W0     = (const float*)d_in[10];
    const float* b0     = (const float*)d_in[11];
    const float* Wm     = (const float*)d_in[12];
    const float* bm     = (const float*)d_in[13];
    const float* Wv     = (const float*)d_in[14];
    const float* bv     = (const float*)d_in[15];
    const float* Wih_h  = (const float*)d_in[16];
    const float* Whh_h  = (const float*)d_in[17];
    const float* bih_h  = (const float*)d_in[18];
    const float* bhh_h  = (const float*)d_in[19];
    const float* Wy     = (const float*)d_in[20];
    const float* by     = (const float*)d_in[21];

    float *p_xT, *p_gates, *p_gx, *p_u0, *p_hdec, *p_bgx;
    cudaGetSymbolAddress((void**)&p_xT,    d_xT);
    cudaGetSymbolAddress((void**)&p_gates, d_gates);
    cudaGetSymbolAddress((void**)&p_gx,    d_gx);
    cudaGetSymbolAddress((void**)&p_u0,    d_u0);
    cudaGetSymbolAddress((void**)&p_hdec,  d_hdec);
    cudaGetSymbolAddress((void**)&p_bgx,   d_bgx);

    cudaFuncSetAttribute(lstm_gx_kernel,   cudaFuncAttributeMaxDynamicSharedMemorySize, SMB_LSTM);
    cudaFuncSetAttribute(lstm_dec_kernel,  cudaFuncAttributeMaxDynamicSharedMemorySize, SMB_LSTM);
    cudaFuncSetAttribute(inference_kernel, cudaFuncAttributeMaxDynamicSharedMemorySize, SMB_INF);

    float* out = (float*)d_out;
    const size_t Y_SZ  = (size_t)BB*XD*TT;
    const size_t MV_SZ = (size_t)BB*ZD*TT;

    prep_weights<<<64, 256>>>(Whh_gx, bih_gx, bhh_gx, Wih_gz, Whh_gz, bih_gz, bhh_gz,
                              W0, Wih_h, Whh_h, bih_h, bhh_h);
    transpose_x<<<dim3(XROWS/32, TT/32), 256>>>(x);

    gemm_tn<2><<<dim3(TT*BB/128, GG/64), 256>>>(p_xT, XD, Wih_gx, XD, p_bgx, p_gates,
                                                TT*BB, GG, XD);
    lstm_gx_kernel<<<2*NCLUST, NTH, SMB_LSTM>>>();
    gemm_tn<0><<<dim3(TT*BB/128, HH/64), 256>>>(p_gx, HH, W0, 2*HH, b0, p_u0,
                                                TT*BB, HH, HH);
    inference_kernel<<<2*NCLUST, NTH, SMB_INF>>>(eps, Wm, bm, Wv, bv,
                                                 out + Y_SZ, out + Y_SZ + MV_SZ,
                                                 out + Y_SZ + 2*MV_SZ);
    lstm_dec_kernel<<<2*NCLUST, NTH, SMB_LSTM>>>();
    gemm_tn<1><<<dim3(TT*BB/128, (XD+63)/64), 256>>>(p_hdec, HH, Wy, HH, by, out,
                                                     TT*BB, XD, HH);
}

// round 17
// speedup vs baseline: 1.5769x; 1.5769x over previous
#include <cuda_runtime.h>
#include <math.h>
#include <stdint.h>

#define TT 512
#define BB 256
#define HH 128
#define XD 257
#define ZD 16
#define GG 512
#define RB 4
#define NCLUST (BB/RB)
#define XROWS (BB*XD)
#define NTH 512

__device__ float d_xT[(size_t)TT*BB*XD];
__device__ float d_gates[(size_t)TT*GG*BB];
__device__ float d_gx[(size_t)TT*BB*HH];
__device__ float d_u0[(size_t)TT*BB*HH];
__device__ float d_zbuf[(size_t)BB*TT*ZD];
__device__ float d_hdec[(size_t)BB*TT*HH];
__device__ float d_WTgx[HH*GG];
__device__ float d_WTgz[HH*GG];
__device__ float d_WTh [HH*GG];
__device__ float d_W0RT[HH*HH];
__device__ float d_WihTgz[ZD*GG];
__device__ float d_WihTh [ZD*GG];
__device__ float d_bgx[GG];
__device__ float d_bgz[GG];
__device__ float d_bh [GG];

typedef unsigned long long u64;

__device__ __forceinline__ float tanha(float x) {
    float y; asm("tanh.approx.f32 %0, %1;" : "=f"(y) : "f"(x)); return y;
}
__device__ __forceinline__ float sigf(float x) { return fmaf(0.5f, tanha(0.5f*x), 0.5f); }
__device__ __forceinline__ u64 pk2(float lo, float hi) {
    u64 r; asm("mov.b64 %0, {%1, %2};" : "=l"(r) : "f"(lo), "f"(hi)); return r;
}
__device__ __forceinline__ void upk2(u64 v, float& lo, float& hi) {
    asm("mov.b64 {%0, %1}, %2;" : "=f"(lo), "=f"(hi) : "l"(v));
}
__device__ __forceinline__ u64 f2fma(u64 a, u64 b, u64 c) {
    u64 d; asm("fma.rn.f32x2 %0, %1, %2, %3;" : "=l"(d) : "l"(a), "l"(b), "l"(c)); return d;
}
__device__ __forceinline__ u64 add2(u64 a, u64 b) {
    u64 d; asm("add.rn.f32x2 %0, %1, %2;" : "=l"(d) : "l"(a), "l"(b)); return d;
}
__device__ __forceinline__ uint32_t s2u(const void* p) {
    uint32_t a; asm("{ .reg .u64 t; cvta.to.shared.u64 t, %1; cvt.u32.u64 %0, t; }" : "=r"(a) : "l"(p)); return a;
}
__device__ __forceinline__ uint32_t mapa_u32(uint32_t a, uint32_t rk) {
    uint32_t o; asm("mapa.shared::cluster.u32 %0, %1, %2;" : "=r"(o) : "r"(a), "r"(rk)); return o;
}
__device__ __forceinline__ void stpeer32(uint32_t a, float v) {
    asm volatile("st.shared::cluster.f32 [%0], %1;" :: "r"(a), "f"(v) : "memory");
}
__device__ __forceinline__ void stpeer64(uint32_t a, u64 v) {
    asm volatile("st.shared::cluster.b64 [%0], %1;" :: "r"(a), "l"(v) : "memory");
}
__device__ __forceinline__ void mbar_init(uint32_t a, uint32_t cnt) {
    asm volatile("mbarrier.init.shared.b64 [%0], %1;" :: "r"(a), "r"(cnt) : "memory");
}
__device__ __forceinline__ void mbar_arrive_local(uint32_t a) {
    asm volatile("mbarrier.arrive.shared.b64 _, [%0];" :: "r"(a) : "memory");
}
__device__ __forceinline__ void mbar_arrive_peer(uint32_t a) {
    asm volatile("mbarrier.arrive.release.cluster.shared::cluster.b64 _, [%0];" :: "r"(a) : "memory");
}
__device__ __forceinline__ void mbar_wait(uint32_t a, uint32_t ph) {
    uint32_t done;
    asm volatile("{\n\t.reg .pred p;\n\t"
        "mbarrier.try_wait.parity.acquire.cta.shared::cta.b64 p, [%1], %2;\n\t"
        "selp.b32 %0, 1, 0, p;\n\t}" : "=r"(done) : "r"(a), "r"(ph) : "memory");
    while (!done) {
        asm volatile("{\n\t.reg .pred p;\n\t"
            "mbarrier.try_wait.parity.acquire.cta.shared::cta.b64 p, [%1], %2, 0x989680;\n\t"
            "selp.b32 %0, 1, 0, p;\n\t}" : "=r"(done) : "r"(a), "r"(ph) : "memory");
    }
}
#define CLUSTER_SYNC() do { \
    asm volatile("barrier.cluster.arrive.aligned;" ::: "memory"); \
    asm volatile("barrier.cluster.wait.aligned;"   ::: "memory"); } while (0)

__device__ __forceinline__ int h_wr_off(int k, int r) {
    return ((k << 5) + (r << 3)) ^ (k & 0x70);
}
__device__ __forceinline__ void gate_hloop(const char* hb, int sw,
        const u64* wif2, const u64* wgo2, u64* aif, u64* ago) {
#pragma unroll
    for (int kk = 0; kk < 16; kk++) {
        int off = (kk*32) ^ sw;
        ulonglong2 h01 = *(const ulonglong2*)(hb + off);
        ulonglong2 h23 = *(const ulonglong2*)(hb + (off ^ 16));
        aif[0]=f2fma(wif2[kk],h01.x,aif[0]); aif[1]=f2fma(wif2[kk],h01.y,aif[1]);
        aif[2]=f2fma(wif2[kk],h23.x,aif[2]); aif[3]=f2fma(wif2[kk],h23.y,aif[3]);
        ago[0]=f2fma(wgo2[kk],h01.x,ago[0]); ago[1]=f2fma(wgo2[kk],h01.y,ago[1]);
        ago[2]=f2fma(wgo2[kk],h23.x,ago[2]); ago[3]=f2fma(wgo2[kk],h23.y,ago[3]);
    }
}
__device__ __forceinline__ void gate_reduce(u64* aif, u64* ago) {
#pragma unroll
    for (int d = 1; d <= 4; d <<= 1)
#pragma unroll
        for (int r = 0; r < 4; r++) {
            aif[r]=add2(aif[r],__shfl_xor_sync(0xffffffffu,aif[r],d));
            ago[r]=add2(ago[r],__shfl_xor_sync(0xffffffffu,ago[r],d));
        }
}
__device__ __forceinline__ void gate_select(int khx, const u64* aif, const u64* ago,
        float& gi, float& gf, float& gg, float& go_) {
    u64 t1=(khx&1)?aif[1]:aif[0], t2=(khx&1)?aif[3]:aif[2];
    u64 vif=(khx&2)?t2:t1;
    u64 u1=(khx&1)?ago[1]:ago[0], u2=(khx&1)?ago[3]:ago[2];
    u64 vgo=(khx&2)?u2:u1;
    upk2(vif,gi,gf); upk2(vgo,gg,go_);
}

__global__ void prep_weights(const float* __restrict__ Whh_gx,
                             const float* __restrict__ bih_gx, const float* __restrict__ bhh_gx,
                             const float* __restrict__ Wih_gz, const float* __restrict__ Whh_gz,
                             const float* __restrict__ bih_gz, const float* __restrict__ bhh_gz,
                             const float* __restrict__ W0,
                             const float* __restrict__ Wih_h, const float* __restrict__ Whh_h,
                             const float* __restrict__ bih_h, const float* __restrict__ bhh_h)
{
    int idx = blockIdx.x*blockDim.x + threadIdx.x;
    int stride = gridDim.x*blockDim.x;
    for (int i = idx; i < GG*HH; i += stride) {
        int j = i / HH, k = i % HH;
        d_WTgx[k*GG + j] = Whh_gx[i];
        d_WTgz[k*GG + j] = Whh_gz[i];
        d_WTh [k*GG + j] = Whh_h [i];
    }
    for (int i = idx; i < HH*HH; i += stride) {
        int j = i / HH, k = i % HH;
        d_W0RT[k*HH + j] = W0[j*(2*HH) + HH + k];
    }
    for (int i = idx; i < GG*ZD; i += stride) {
        int j = i / ZD, k = i % ZD;
        d_WihTgz[k*GG + j] = Wih_gz[i];
        d_WihTh [k*GG + j] = Wih_h [i];
    }
    for (int i = idx; i < GG; i += stride) {
        d_bgx[i] = bih_gx[i] + bhh_gx[i];
        d_bgz[i] = bih_gz[i] + bhh_gz[i];
        d_bh [i] = bih_h [i] + bhh_h [i];
    }
}

__global__ void __launch_bounds__(256) transpose_x(const float* __restrict__ x)
{
    __shared__ float tile[32][33];
    int r0 = blockIdx.x*32, c0 = blockIdx.y*32;
    int tx = threadIdx.x & 31, ty = threadIdx.x >> 5;
#pragma unroll
    for (int i = 0; i < 32; i += 8)
        tile[ty+i][tx] = x[(size_t)(r0+ty+i)*TT + c0 + tx];
    __syncthreads();
#pragma unroll
    for (int i = 0; i < 32; i += 8)
        d_xT[(size_t)(c0+ty+i)*XROWS + r0 + tx] = tile[tx][ty+i];
}

template<int MODE>
__global__ void __launch_bounds__(256)
gemm_tn(const float* __restrict__ A, int lda,
        const float* __restrict__ Bw, int ldb,
        const float* __restrict__ bias,
        float* __restrict__ C, int M, int N, int K)
{
    const int BM = 128, BN = 64, BK = 16;
    __shared__ float As[BK][BM];
    __shared__ u64 Bs2[BK][BN];
    int tid = threadIdx.x;
    int bm = blockIdx.x*BM, bn = blockIdx.y*BN;
    int tm = (tid & 15)*8, tn = (tid >> 4)*4;
    u64 acc[4][4];
#pragma unroll
    for (int p = 0; p < 4; p++)
#pragma unroll
        for (int j = 0; j < 4; j++) acc[p][j] = 0ull;
    int ar = tid >> 1, ac = (tid & 1)*8;
    int br = tid >> 2, bc = (tid & 3)*4;
    for (int kk = 0; kk < K; kk += BK) {
#pragma unroll
        for (int i = 0; i < 8; i++) {
            int k = kk + ac + i;
            As[ac+i][ar] = (k < K) ? A[(size_t)(bm+ar)*lda + k] : 0.f;
        }
#pragma unroll
        for (int i = 0; i < 4; i++) {
            int k = kk + bc + i;
            float bv = (k < K && (bn+br) < N) ? Bw[(size_t)(bn+br)*ldb + k] : 0.f;
            Bs2[bc+i][br] = pk2(bv, bv);
        }
        __syncthreads();
#pragma unroll
        for (int k = 0; k < BK; k++) {
            ulonglong2 aA = *(const ulonglong2*)(&As[k][tm]);
            ulonglong2 aB = *(const ulonglong2*)(&As[k][tm+4]);
            ulonglong2 b01 = *(const ulonglong2*)(&Bs2[k][tn]);
            ulonglong2 b23 = *(const ulonglong2*)(&Bs2[k][tn+2]);
            acc[0][0] = f2fma(aA.x, b01.x, acc[0][0]);
            acc[1][0] = f2fma(aA.y, b01.x, acc[1][0]);
            acc[2][0] = f2fma(aB.x, b01.x, acc[2][0]);
            acc[3][0] = f2fma(aB.y, b01.x, acc[3][0]);
            acc[0][1] = f2fma(aA.x, b01.y, acc[0][1]);
            acc[1][1] = f2fma(aA.y, b01.y, acc[1][1]);
            acc[2][1] = f2fma(aB.x, b01.y, acc[2][1]);
            acc[3][1] = f2fma(aB.y, b01.y, acc[3][1]);
            acc[0][2] = f2fma(aA.x, b23.x, acc[0][2]);
            acc[1][2] = f2fma(aA.y, b23.x, acc[1][2]);
            acc[2][2] = f2fma(aB.x, b23.x, acc[2][2]);
            acc[3][2] = f2fma(aB.y, b23.x, acc[3][2]);
            acc[0][3] = f2fma(aA.x, b23.y, acc[0][3]);
            acc[1][3] = f2fma(aA.y, b23.y, acc[1][3]);
            acc[2][3] = f2fma(aB.x, b23.y, acc[2][3]);
            acc[3][3] = f2fma(aB.y, b23.y, acc[3][3]);
        }
        __syncthreads();
    }
#pragma unroll
    for (int j = 0; j < 4; j++) {
        int n = bn + tn + j;
        if (n >= N) continue;
        float bi = bias[n];
#pragma unroll
        for (int p = 0; p < 4; p++) {
            float v0, v1; upk2(acc[p][j], v0, v1);
            int m0 = bm + tm + 2*p;
            if (MODE == 0) {
                C[(size_t)m0*N + n]     = v0 + bi;
                C[(size_t)(m0+1)*N + n] = v1 + bi;
            } else if (MODE == 2) {
                int t = m0 >> 8, b = m0 & 255;
                C[((size_t)t*GG + n)*BB + b]     = v0 + bi;
                C[((size_t)t*GG + n)*BB + b + 1] = v1 + bi;
            } else {
                int b = m0 >> 9, t = m0 & 511;
                C[(size_t)b*XD*TT + (size_t)n*TT + t] = __expf(v0 + bi);
                int m1 = m0 + 1;
                b = m1 >> 9; t = m1 & 511;
                C[(size_t)b*XD*TT + (size_t)n*TT + t] = __expf(v1 + bi);
            }
        }
    }
}

// ===== LSTM smem (bytes): mbar 16 | h4d 3x4096 | z4d 3x512
#define SB_MB    0
#define SB_H4D   16
#define SB_Z4D   (16 + 12288)
#define SMB_LSTM (16 + 12288 + 1536)

__global__ void __launch_bounds__(NTH,1) __cluster_dims__(2,1,1)
lstm_gx_kernel()
{
    extern __shared__ char smc[];
    char* h4d = smc + SB_H4D;
    uint32_t mb = s2u(smc + SB_MB);
    int tid = threadIdx.x;
    int l = tid & 31, w = tid >> 5;
    int khx = l & 7;
    int hi  = w*4 + (l >> 3);
    uint32_t rank = blockIdx.x & 1u;
    int b0 = (blockIdx.x >> 1) * RB;
    int hig = (int)rank*64 + hi;

    u64 wif2[16], wgo2[16];
#pragma unroll
    for (int kk = 0; kk < 16; kk++) {
        int k = khx*16 + kk;
        wif2[kk] = pk2(d_WTgx[k*GG + hig],       d_WTgx[k*GG + 128 + hig]);
        wgo2[kk] = pk2(d_WTgx[k*GG + 256 + hig], d_WTgx[k*GG + 384 + hig]);
    }
    for (int i = tid; i < 1024; i += NTH) ((float*)h4d)[i] = 0.f;
    if (tid == 0) mbar_init(mb, 768);
    float c_ = 0.f;
    __syncthreads();
    CLUSTER_SYNC();
    uint32_t peer_base = mapa_u32(s2u(smc), rank ^ 1u);
    uint32_t mb_peer = peer_base + SB_MB;

    bool ldr = (khx == 0);
    float4 pgi, pgf, pgg, pgo;
    if (ldr) {
        const float* gp = d_gates + (size_t)(TT-1)*GG*BB + b0;
        pgi = *(const float4*)(gp + (size_t)hig*BB);
        pgf = *(const float4*)(gp + (size_t)(128+hig)*BB);
        pgg = *(const float4*)(gp + (size_t)(256+hig)*BB);
        pgo = *(const float4*)(gp + (size_t)(384+hig)*BB);
    }
    const int sw = khx << 4;
    int br = 0, bw = 1;

    for (int t = TT-1, s = 0; t >= 0; --t, ++s) {
        u64 aif[4], ago[4];
        if (ldr) {
            aif[0]=pk2(pgi.x,pgf.x); aif[1]=pk2(pgi.y,pgf.y);
            aif[2]=pk2(pgi.z,pgf.z); aif[3]=pk2(pgi.w,pgf.w);
            ago[0]=pk2(pgg.x,pgo.x); ago[1]=pk2(pgg.y,pgo.y);
            ago[2]=pk2(pgg.z,pgo.z); ago[3]=pk2(pgg.w,pgo.w);
            if (t > 0) {
                const float* gp = d_gates + (size_t)(t-1)*GG*BB + b0;
                pgi = *(const float4*)(gp + (size_t)hig*BB);
                pgf = *(const float4*)(gp + (size_t)(128+hig)*BB);
                pgg = *(const float4*)(gp + (size_t)(256+hig)*BB);
                pgo = *(const float4*)(gp + (size_t)(384+hig)*BB);
            }
        } else {
#pragma unroll
            for (int r = 0; r < 4; r++) { aif[r] = 0ull; ago[r] = 0ull; }
        }
        gate_hloop(h4d + br*4096 + khx*512, sw, wif2, wgo2, aif, ago);
        gate_reduce(aif, ago);
        float hkeep = 0.f;
        int r = khx;
        if (khx < 4) {
            float gi, gf, gg, go_;
            gate_select(khx, aif, ago, gi, gf, gg, go_);
            float i_ = sigf(gi), f_ = sigf(gf), g_ = tanha(gg), o_ = sigf(go_);
            c_ = f_*c_ + i_*g_;
            float h = o_*tanha(c_);
            hkeep = h;
            u64 hdup = pk2(h, h);
            int woff = bw*4096 + h_wr_off(hig, r);
            *(u64*)(h4d + woff) = hdup;
            stpeer64(peer_base + SB_H4D + (uint32_t)woff, hdup);
            mbar_arrive_peer(mb_peer);
        }
        mbar_arrive_local(mb);
        if (khx < 4)
            d_gx[((size_t)t*BB + b0 + r)*HH + hig] = hkeep;
        mbar_wait(mb, s & 1);
        br = bw; bw = (bw == 2) ? 0 : bw + 1;
    }
}

__global__ void __launch_bounds__(NTH,1) __cluster_dims__(2,1,1)
lstm_dec_kernel()
{
    extern __shared__ char smc[];
    char* h4d = smc + SB_H4D;
    char* z4d = smc + SB_Z4D;
    uint32_t mb = s2u(smc + SB_MB);
    int tid = threadIdx.x;
    int l = tid & 31, w = tid >> 5;
    int khx = l & 7;
    int hi  = w*4 + (l >> 3);
    uint32_t rank = blockIdx.x & 1u;
    int b0 = (blockIdx.x >> 1) * RB;
    int hig = (int)rank*64 + hi;

    u64 wif2[16], wgo2[16];
#pragma unroll
    for (int kk = 0; kk < 16; kk++) {
        int k = khx*16 + kk;
        wif2[kk] = pk2(d_WTh[k*GG + hig],       d_WTh[k*GG + 128 + hig]);
        wgo2[kk] = pk2(d_WTh[k*GG + 256 + hig], d_WTh[k*GG + 384 + hig]);
    }
    u64 wzif2[2], wzgo2[2];
#pragma unroll
    for (int jz = 0; jz < 2; jz++) {
        int zk = khx*2 + jz;
        wzif2[jz] = pk2(d_WihTh[zk*GG + hig],       d_WihTh[zk*GG + 128 + hig]);
        wzgo2[jz] = pk2(d_WihTh[zk*GG + 256 + hig], d_WihTh[zk*GG + 384 + hig]);
    }
    u64 bif2 = pk2(d_bh[hig],       d_bh[128 + hig]);
    u64 bgo2 = pk2(d_bh[256 + hig], d_bh[384 + hig]);

    for (int i = tid; i < 1024; i += NTH) ((float*)h4d)[i] = 0.f;
    float znext = 0.f;
    int zr = tid >> 4, zzi = tid & 15;
    if (tid < 64) {
        float z0 = d_zbuf[((size_t)(b0+zr)*TT + 0)*ZD + zzi];
        *(u64*)(z4d + zzi*32 + zr*8) = pk2(z0, z0);
        znext = d_zbuf[((size_t)(b0+zr)*TT + 1)*ZD + zzi];
    }
    if (tid == 0) mbar_init(mb, 768);
    float c_ = 0.f;
    __syncthreads();
    CLUSTER_SYNC();
    uint32_t peer_base = mapa_u32(s2u(smc), rank ^ 1u);
    uint32_t mb_peer = peer_base + SB_MB;
    const int sw = khx << 4;
    int br = 0, bw = 1;

    for (int t = 0, s = 0; t < TT; ++t, ++s) {
        if (tid < 64 && t+1 < TT) {
            *(u64*)(z4d + bw*512 + zzi*32 + zr*8) = pk2(znext, znext);
            if (t+2 < TT)
                znext = d_zbuf[((size_t)(b0+zr)*TT + (t+2))*ZD + zzi];
        }
        u64 aif[4], ago[4];
        if (khx == 0) {
#pragma unroll
            for (int r = 0; r < 4; r++) { aif[r] = bif2; ago[r] = bgo2; }
        } else {
#pragma unroll
            for (int r = 0; r < 4; r++) { aif[r] = 0ull; ago[r] = 0ull; }
        }
        const char* zb = z4d + br*512;
#pragma unroll
        for (int jz = 0; jz < 2; jz++) {
            int zk = khx*2 + jz;
            ulonglong2 z01 = *(const ulonglong2*)(zb + zk*32);
            ulonglong2 z23 = *(const ulonglong2*)(zb + zk*32 + 16);
            aif[0]=f2fma(wzif2[jz],z01.x,aif[0]); aif[1]=f2fma(wzif2[jz],z01.y,aif[1]);
            aif[2]=f2fma(wzif2[jz],z23.x,aif[2]); aif[3]=f2fma(wzif2[jz],z23.y,aif[3]);
            ago[0]=f2fma(wzgo2[jz],z01.x,ago[0]); ago[1]=f2fma(wzgo2[jz],z01.y,ago[1]);
            ago[2]=f2fma(wzgo2[jz],z23.x,ago[2]); ago[3]=f2fma(wzgo2[jz],z23.y,ago[3]);
        }
        gate_hloop(h4d + br*4096 + khx*512, sw, wif2, wgo2, aif, ago);
        gate_reduce(aif, ago);
        float hkeep = 0.f;
        int r = khx;
        if (khx < 4) {
            float gi, gf, gg, go_;
            gate_select(khx, aif, ago, gi, gf, gg, go_);
            float i_ = sigf(gi), f_ = sigf(gf), g_ = tanha(gg), o_ = sigf(go_);
            c_ = f_*c_ + i_*g_;
            float h = o_*tanha(c_);
            hkeep = h;
            u64 hdup = pk2(h, h);
            int woff = bw*4096 + h_wr_off(hig, r);
            *(u64*)(h4d + woff) = hdup;
            stpeer64(peer_base + SB_H4D + (uint32_t)woff, hdup);
            mbar_arrive_peer(mb_peer);
        }
        mbar_arrive_local(mb);
        if (khx < 4)
            d_hdec[((size_t)(b0+r)*TT + t)*HH + hig] = hkeep;
        mbar_wait(mb, s & 1);
        br = bw; bw = (bw == 2) ? 0 : bw + 1;
    }
}

// ===== inference smem (bytes)
#define SBI_MBH  0
#define SBI_MBZ  8
#define SBI_H4D  16
#define SBI_Z4D  (16 + 12288)
#define SBI_H4P  (SBI_Z4D + 1536)
#define SBI_W0R  (SBI_H4P + 6144)
#define SBI_WHD  (SBI_W0R + 65536)
#define SBI_HM   (SBI_WHD + 16896)
#define SBI_MV   (SBI_HM + 1024)
#define SMB_INF  (SBI_MV + 256)

__global__ void __launch_bounds__(NTH,1) __cluster_dims__(2,1,1)
inference_kernel(const float* __restrict__ eps,
                 const float* __restrict__ Wm, const float* __restrict__ bm,
                 const float* __restrict__ Wv, const float* __restrict__ bv,
                 float* __restrict__ out_mean, float* __restrict__ out_logvar,
                 float* __restrict__ out_z)
{
    extern __shared__ char smc[];
    char*  h4d = smc + SBI_H4D;
    char*  z4d = smc + SBI_Z4D;
    float* h4p = (float*)(smc + SBI_H4P);
    float* W0R = (float*)(smc + SBI_W0R);
    float* whd = (float*)(smc + SBI_WHD);
    float* hm  = (float*)(smc + SBI_HM);
    float* mv  = (float*)(smc + SBI_MV);
    uint32_t mbh = s2u(smc + SBI_MBH);
    uint32_t mbz = s2u(smc + SBI_MBZ);
    int tid = threadIdx.x;
    int l = tid & 31, w = tid >> 5;
    int khx = l & 7;
    int hi  = w*4 + (l >> 3);
    uint32_t rank = blockIdx.x & 1u;
    int b0 = (blockIdx.x >> 1) * RB;
    int hig = (int)rank*64 + hi;

    u64 wif2[16], wgo2[16];
#pragma unroll
    for (int kk = 0; kk < 16; kk++) {
        int k = khx*16 + kk;
        wif2[kk] = pk2(d_WTgz[k*GG + hig],       d_WTgz[k*GG + 128 + hig]);
        wgo2[kk] = pk2(d_WTgz[k*GG + 256 + hig], d_WTgz[k*GG + 384 + hig]);
    }
    u64 wzif2[2], wzgo2[2];
#pragma unroll
    for (int jz = 0; jz < 2; jz++) {
        int zk = khx*2 + jz;
        wzif2[jz] = pk2(d_WihTgz[zk*GG + hig],       d_WihTgz[zk*GG + 128 + hig]);
        wzgo2[jz] = pk2(d_WihTgz[zk*GG + 256 + hig], d_WihTgz[zk*GG + 384 + hig]);
    }
    u64 bif2 = pk2(d_bgz[hig],       d_bgz[128 + hig]);
    u64 bgo2 = pk2(d_bgz[256 + hig], d_bgz[384 + hig]);

    for (int i = tid; i < HH*HH; i += NTH) W0R[i] = d_W0RT[i];
    for (int i = tid; i < 32*HH; i += NTH) {
        int row = i >> 7, k = i & 127;
        whd[row*132 + k] = (row < 16) ? Wm[row*HH + k] : Wv[(row-16)*HH + k];
    }
    int outv = tid >> 3, kq = tid & 7;
    int rr_h = (outv >> 5) & 1, head = (outv >> 4) & 1, zi_h = outv & 15;
    float hbias = head ? bv[zi_h] : bm[zi_h];
    int jm = tid & 127, rrm = (tid >> 7) & 1;
    int browm = b0 + rank*2 + rrm;
    int hidxm = rank*2 + rrm;
    int rr_z = (tid >> 4) & 1, zi_z = tid & 15;
    int brow_z = b0 + rank*2 + rr_z;

    for (int i = tid; i < 1024; i += NTH) ((float*)h4d)[i] = 0.f;
    for (int i = tid; i < 512; i += NTH)  h4p[i] = 0.f;
    if (tid == 0) { mbar_init(mbh, 768); mbar_init(mbz, 544); }
    float c_ = 0.f;
    __syncthreads();
    CLUSTER_SYNC();
    uint32_t peer_base = mapa_u32(s2u(smc), rank ^ 1u);
    uint32_t mbh_peer = peer_base + SBI_MBH;
    uint32_t mbz_peer = peer_base + SBI_MBZ;

    float u0pf = 0.f, epf = 0.f;
    if (tid < 256) u0pf = d_u0[((size_t)0*BB + browm)*HH + jm];
    if (tid < 32)  epf  = eps[((size_t)0*BB + brow_z)*ZD + zi_z];

    const int sw = khx << 4;
    int br = 0, bw = 1;

    for (int t = 0, s = 0; t < TT; ++t, ++s) {
        float u0c = u0pf, ec = epf;
        if (t+1 < TT) {
            if (tid < 256) u0pf = d_u0[((size_t)(t+1)*BB + browm)*HH + jm];
            if (tid < 32)  epf  = eps[((size_t)(t+1)*BB + brow_z)*ZD + zi_z];
        }
        if (tid < 256) {
            const float* hp = h4p + br*512 + hidxm;
            float a0 = u0c, a1 = 0.f, a2 = 0.f, a3 = 0.f;
#pragma unroll
            for (int k = 0; k < HH; k += 4) {
                a0 += W0R[k*HH + jm]     * hp[k*4];
                a1 += W0R[(k+1)*HH + jm] * hp[(k+1)*4];
                a2 += W0R[(k+2)*HH + jm] * hp[(k+2)*4];
                a3 += W0R[(k+3)*HH + jm] * hp[(k+3)*4];
            }
            hm[rrm*HH + jm] = tanha((a0+a1) + (a2+a3));
        }
        __syncthreads();
        {
            const float* wrow = whd + (head*16 + zi_h)*132 + kq*16;
            const float* hr   = hm + rr_h*HH + kq*16;
            float s0=0.f, s1=0.f, s2=0.f, s3=0.f;
#pragma unroll
            for (int kk = 0; kk < 16; kk += 4) {
                float4 wv4 = *(const float4*)(wrow + kk);
                float4 hv4 = *(const float4*)(hr + kk);
                s0 += wv4.x*hv4.x; s1 += wv4.y*hv4.y;
                s2 += wv4.z*hv4.z; s3 += wv4.w*hv4.w;
            }
            float acc = (s0+s1) + (s2+s3);
            acc += __shfl_xor_sync(0xffffffffu, acc, 1);
            acc += __shfl_xor_sync(0xffffffffu, acc, 2);
            acc += __shfl_xor_sync(0xffffffffu, acc, 4);
            if (kq == 0) mv[outv] = acc + hbias;
        }
        __syncthreads();
        int zslot = br*512;
        float mn = 0.f, lv = 0.f, zv = 0.f;
        if (tid < 32) {
            mn = mv[rr_z*32 + zi_z];
            lv = mv[rr_z*32 + 16 + zi_z];
            zv = ec*__expf(0.5f*lv) + mn;
            u64 zdup = pk2(zv, zv);
            int zo = zslot + zi_z*32 + (int)(rank*2 + rr_z)*8;
            *(u64*)(z4d + zo) = zdup;
            stpeer64(peer_base + SBI_Z4D + (uint32_t)zo, zdup);
            mbar_arrive_peer(mbz_peer);
        }
        mbar_arrive_local(mbz);
        if (tid < 32) {
            size_t oidx = (size_t)brow_z*ZD*TT + (size_t)zi_z*TT + t;
            out_mean[oidx]   = mn;
            out_logvar[oidx] = lv;
            out_z[oidx]      = zv;
            d_zbuf[((size_t)brow_z*TT + t)*ZD + zi_z] = zv;
        }
        mbar_wait(mbz, s & 1);
        u64 aif[4], ago[4];
        if (khx == 0) {
#pragma unroll
            for (int r = 0; r < 4; r++) { aif[r] = bif2; ago[r] = bgo2; }
        } else {
#pragma unroll
            for (int r = 0; r < 4; r++) { aif[r] = 0ull; ago[r] = 0ull; }
        }
        const char* zb = z4d + zslot;
#pragma unroll
        for (int jz = 0; jz < 2; jz++) {
            int zk = khx*2 + jz;
            ulonglong2 z01 = *(const ulonglong2*)(zb + zk*32);
            ulonglong2 z23 = *(const ulonglong2*)(zb + zk*32 + 16);
            aif[0]=f2fma(wzif2[jz],z01.x,aif[0]); aif[1]=f2fma(wzif2[jz],z01.y,aif[1]);
            aif[2]=f2fma(wzif2[jz],z23.x,aif[2]); aif[3]=f2fma(wzif2[jz],z23.y,aif[3]);
            ago[0]=f2fma(wzgo2[jz],z01.x,ago[0]); ago[1]=f2fma(wzgo2[jz],z01.y,ago[1]);
            ago[2]=f2fma(wzgo2[jz],z23.x,ago[2]); ago[3]=f2fma(wzgo2[jz],z23.y,ago[3]);
        }
        gate_hloop(h4d + br*4096 + khx*512, sw, wif2, wgo2, aif, ago);
        gate_reduce(aif, ago);
        if (khx < 4) {
            int r = khx;
            float gi, gf, gg, go_;
            gate_select(khx, aif, ago, gi, gf, gg, go_);
            float i_ = sigf(gi), f_ = sigf(gf), g_ = tanha(gg), o_ = sigf(go_);
            c_ = f_*c_ + i_*g_;
            float h = o_*tanha(c_);
            u64 hdup = pk2(h, h);
            int woff = bw*4096 + h_wr_off(hig, r);
            *(u64*)(h4d + woff) = hdup;
            stpeer64(peer_base + SBI_H4D + (uint32_t)woff, hdup);
            int poff = bw*512 + hig*4 + r;
            h4p[poff] = h;
            stpeer32(peer_base + SBI_H4P + (uint32_t)poff*4u, h);
            mbar_arrive_peer(mbh_peer);
        }
        mbar_arrive_local(mbh);
        mbar_wait(mbh, s & 1);
        br = bw; bw = (bw == 2) ? 0 : bw + 1;
    }
}

extern "C" void kernel_launch(void* const* d_in, const int* in_sizes, int n_in,
                              void* d_out, int out_size)
{
    (void)in_sizes; (void)n_in; (void)out_size;
    const float* x      = (const float*)d_in[0];
    const float* eps    = (const float*)d_in[1];
    const float* Wih_gx = (const float*)d_in[2];
    const float* Whh_gx = (const float*)d_in[3];
    const float* bih_gx = (const float*)d_in[4];
    const float* bhh_gx = (const float*)d_in[5];
    const float* Wih_gz = (const float*)d_in[6];
    const float* Whh_gz = (const float*)d_in[7];
    const float* bih_gz = (const float*)d_in[8];
    const float* bhh_gz = (const float*)d_in[9];
    const float* W0     = (const float*)d_in[10];
    const float* b0     = (const float*)d_in[11];
    const float* Wm     = (const float*)d_in[12];
    const float* bm     = (const float*)d_in[13];
    const float* Wv     = (const float*)d_in[14];
    const float* bv     = (const float*)d_in[15];
    const float* Wih_h  = (const float*)d_in[16];
    const float* Whh_h  = (const float*)d_in[17];
    const float* bih_h  = (const float*)d_in[18];
    const float* bhh_h  = (const float*)d_in[19];
    const float* Wy     = (const float*)d_in[20];
    const float* by     = (const float*)d_in[21];

    float *p_xT, *p_gates, *p_gx, *p_u0, *p_hdec, *p_bgx;
    cudaGetSymbolAddress((void**)&p_xT,    d_xT);
    cudaGetSymbolAddress((void**)&p_gates, d_gates);
    cudaGetSymbolAddress((void**)&p_gx,    d_gx);
    cudaGetSymbolAddress((void**)&p_u0,    d_u0);
    cudaGetSymbolAddress((void**)&p_hdec,  d_hdec);
    cudaGetSymbolAddress((void**)&p_bgx,   d_bgx);

    cudaFuncSetAttribute(lstm_gx_kernel,   cudaFuncAttributeMaxDynamicSharedMemorySize, SMB_LSTM);
    cudaFuncSetAttribute(lstm_dec_kernel,  cudaFuncAttributeMaxDynamicSharedMemorySize, SMB_LSTM);
    cudaFuncSetAttribute(inference_kernel, cudaFuncAttributeMaxDynamicSharedMemorySize, SMB_INF);

    float* out = (float*)d_out;
    const size_t Y_SZ  = (size_t)BB*XD*TT;
    const size_t MV_SZ = (size_t)BB*ZD*TT;

    prep_weights<<<64, 256>>>(Whh_gx, bih_gx, bhh_gx, Wih_gz, Whh_gz, bih_gz, bhh_gz,
                              W0, Wih_h, Whh_h, bih_h, bhh_h);
    transpose_x<<<dim3(XROWS/32, TT/32), 256>>>(x);

    gemm_tn<2><<<dim3(TT*BB/128, GG/64), 256>>>(p_xT, XD, Wih_gx, XD, p_bgx, p_gates,
                                                TT*BB, GG, XD);
    lstm_gx_kernel<<<2*NCLUST, NTH, SMB_LSTM>>>();
    gemm_tn<0><<<dim3(TT*BB/128, HH/64), 256>>>(p_gx, HH, W0, 2*HH, b0, p_u0,
                                                TT*BB, HH, HH);
    inference_kernel<<<2*NCLUST, NTH, SMB_INF>>>(eps, Wm, bm, Wv, bv,
                                                 out + Y_SZ, out + Y_SZ + MV_SZ,
                                                 out + Y_SZ + 2*MV_SZ);
    lstm_dec_kernel<<<2*NCLUST, NTH, SMB_LSTM>>>();
    gemm_tn<1><<<dim3(TT*BB/128, (XD+63)/64), 256>>>(p_hdec, HH, Wy, HH, by, out,
                                                     TT*BB, XD, HH);
}